// round 4
// baseline (speedup 1.0000x reference)
#include <cuda_runtime.h>
#include <cfloat>
#include <math.h>

#define BS    4096
#define INDIM 1024
#define HEADS 4
#define KDIM  512
#define HALF  256
#define NKEYS 512
#define KNN   32
#define VDIM  1024
#define QCOLS (HEADS*KDIM)   /* 2048 */

// Scratch (static device allocations are permitted; no runtime alloc)
__device__ float g_q[(size_t)BS * QCOLS];                  // 32 MB
__device__ float g_scores[(size_t)BS * HEADS * 2 * NKEYS]; // 64 MB
__device__ float g_w[(size_t)BS * HEADS * KNN];            // 2 MB
__device__ int   g_idx[(size_t)BS * HEADS * KNN];          // 2 MB

// ---------------------------------------------------------------------------
// K1: q = x @ w_query    C(4096x2048) = A(4096x1024) * B(1024x2048), row-major
// 128x128 tile, BK=8, 256 threads, 8x8 microtile (split 4+4 for LDS.128)
// ---------------------------------------------------------------------------
__global__ __launch_bounds__(256) void k1_gemm(const float* __restrict__ A,
                                               const float* __restrict__ B) {
    const int K = INDIM, N = QCOLS;
    __shared__ float As[8][128];
    __shared__ float Bs[8][128];
    const int tid = threadIdx.x;
    const int tr = tid >> 4, tc = tid & 15;
    const int bm = blockIdx.y * 128, bn = blockIdx.x * 128;
    const int arow = tid >> 1, acol = (tid & 1) * 4;
    const int brow = tid >> 5, bcol = (tid & 31) * 4;
    const float* Aptr = A + (size_t)(bm + arow) * K + acol;
    const float* Bptr = B + (size_t)brow * N + bn + bcol;
    float acc[8][8] = {};

    for (int k0 = 0; k0 < K; k0 += 8) {
        float4 a = *(const float4*)(Aptr + k0);
        As[acol + 0][arow] = a.x;
        As[acol + 1][arow] = a.y;
        As[acol + 2][arow] = a.z;
        As[acol + 3][arow] = a.w;
        *(float4*)&Bs[brow][bcol] = *(const float4*)(Bptr + (size_t)k0 * N);
        __syncthreads();
#pragma unroll
        for (int k = 0; k < 8; k++) {
            float4 a0 = *(const float4*)&As[k][tr * 4];
            float4 a1 = *(const float4*)&As[k][64 + tr * 4];
            float4 b0 = *(const float4*)&Bs[k][tc * 4];
            float4 b1 = *(const float4*)&Bs[k][64 + tc * 4];
            float ra[8] = {a0.x, a0.y, a0.z, a0.w, a1.x, a1.y, a1.z, a1.w};
            float rb[8] = {b0.x, b0.y, b0.z, b0.w, b1.x, b1.y, b1.z, b1.w};
#pragma unroll
            for (int i = 0; i < 8; i++)
#pragma unroll
                for (int j = 0; j < 8; j++)
                    acc[i][j] += ra[i] * rb[j];
        }
        __syncthreads();
    }
#pragma unroll
    for (int i = 0; i < 8; i++) {
        int row = bm + ((i < 4) ? (tr * 4 + i) : (64 + tr * 4 + i - 4));
        float* Crow = g_q + (size_t)row * N + bn;
        *(float4*)(Crow + tc * 4)      = make_float4(acc[i][0], acc[i][1], acc[i][2], acc[i][3]);
        *(float4*)(Crow + 64 + tc * 4) = make_float4(acc[i][4], acc[i][5], acc[i][6], acc[i][7]);
    }
}

// ---------------------------------------------------------------------------
// K2: scores[b,h,s,n] = sum_d q[b,h,s,d] * keys[h,s,n,d]   (NT GEMM per (h,s))
// A: g_q + p*256, row stride 2048 ; B: keys + p*512*256, row stride 256
// C: g_scores + p*512, row stride 4096. Tile 128x128, BK=8.
// ---------------------------------------------------------------------------
__global__ __launch_bounds__(256) void k2_scores(const float* __restrict__ keys) {
    const int p = blockIdx.z;                         // h*2+s
    const float* A = g_q + (size_t)p * HALF;          // h*512+s*256 == p*256
    const float* B = keys + (size_t)p * NKEYS * HALF;
    float* C = g_scores + (size_t)p * NKEYS;
    __shared__ float As[8][128];
    __shared__ float Bs[8][128];
    const int tid = threadIdx.x;
    const int tr = tid >> 4, tc = tid & 15;
    const int bm = blockIdx.y * 128, bn = blockIdx.x * 128;
    const int arow = tid >> 1, acol = (tid & 1) * 4;
    const float* Aptr = A + (size_t)(bm + arow) * QCOLS + acol;
    const float* Bptr = B + (size_t)(bn + arow) * HALF + acol;
    float acc[8][8] = {};

    for (int k0 = 0; k0 < HALF; k0 += 8) {
        float4 a = *(const float4*)(Aptr + k0);
        As[acol + 0][arow] = a.x;
        As[acol + 1][arow] = a.y;
        As[acol + 2][arow] = a.z;
        As[acol + 3][arow] = a.w;
        float4 b = *(const float4*)(Bptr + k0);
        Bs[acol + 0][arow] = b.x;
        Bs[acol + 1][arow] = b.y;
        Bs[acol + 2][arow] = b.z;
        Bs[acol + 3][arow] = b.w;
        __syncthreads();
#pragma unroll
        for (int k = 0; k < 8; k++) {
            float4 a0 = *(const float4*)&As[k][tr * 4];
            float4 a1 = *(const float4*)&As[k][64 + tr * 4];
            float4 b0 = *(const float4*)&Bs[k][tc * 4];
            float4 b1 = *(const float4*)&Bs[k][64 + tc * 4];
            float ra[8] = {a0.x, a0.y, a0.z, a0.w, a1.x, a1.y, a1.z, a1.w};
            float rb[8] = {b0.x, b0.y, b0.z, b0.w, b1.x, b1.y, b1.z, b1.w};
#pragma unroll
            for (int i = 0; i < 8; i++)
#pragma unroll
                for (int j = 0; j < 8; j++)
                    acc[i][j] += ra[i] * rb[j];
        }
        __syncthreads();
    }
#pragma unroll
    for (int i = 0; i < 8; i++) {
        int row = bm + ((i < 4) ? (tr * 4 + i) : (64 + tr * 4 + i - 4));
        float* Crow = C + (size_t)row * (8 * NKEYS) + bn;
        *(float4*)(Crow + tc * 4)      = make_float4(acc[i][0], acc[i][1], acc[i][2], acc[i][3]);
        *(float4*)(Crow + 64 + tc * 4) = make_float4(acc[i][4], acc[i][5], acc[i][6], acc[i][7]);
    }
}

// ---------------------------------------------------------------------------
// K3: per (b,h): top-32 of each 512-score list, staircase top-32 of the
// 32x32 cartesian sum grid, softmax. One warp per (b,h).
// ---------------------------------------------------------------------------
__device__ __forceinline__ void warp_argmax(float& rv, int& rm) {
#pragma unroll
    for (int o = 16; o > 0; o >>= 1) {
        float ov = __shfl_down_sync(0xffffffffu, rv, o);
        int   om = __shfl_down_sync(0xffffffffu, rm, o);
        if (ov > rv || (ov == rv && om < rm)) { rv = ov; rm = om; }
    }
    rv = __shfl_sync(0xffffffffu, rv, 0);
    rm = __shfl_sync(0xffffffffu, rm, 0);
}

__global__ __launch_bounds__(128) void k3_topk() {
    const unsigned FULL = 0xffffffffu;
    const int b = blockIdx.x;
    const int h = threadIdx.x >> 5;
    const int lane = threadIdx.x & 31;

    // Phase A: top-32 of 512 for s=0,1. Lane r ends holding rank-r (value, index).
    float selv[2];
    int   seli[2];
#pragma unroll
    for (int s = 0; s < 2; s++) {
        const float* S = g_scores + ((size_t)(b * HEADS + h) * 2 + s) * NKEYS;
        float v[16];
#pragma unroll
        for (int i = 0; i < 16; i++) v[i] = S[i * 32 + lane];
        float mysel = 0.f; int myi = 0;
        for (int t = 0; t < KNN; t++) {
            float lv = -FLT_MAX; int ls = 0;
#pragma unroll
            for (int i = 0; i < 16; i++)
                if (v[i] > lv) { lv = v[i]; ls = i; }
            float rv = lv; int rm = ls * 32 + lane;   // element index (tie -> lowest)
            warp_argmax(rv, rm);
            if ((rm & 31) == lane) v[rm >> 5] = -FLT_MAX;
            if (lane == t) { mysel = rv; myi = rm; }
        }
        selv[s] = mysel; seli[s] = myi;
    }

    // Phase B: staircase top-32 over cart[i][j] = s1[i] + s2[j], both sorted desc.
    const float av = selv[0]; const int ai = seli[0];
    const float bv = selv[1]; const int bi = seli[1];
    int ptr = 0;
    float myval = 0.f; int myidx = 0;
    for (int t = 0; t < KNN; t++) {
        float s2v = __shfl_sync(FULL, bv, ptr & 31);
        float rv = (ptr < KNN) ? (av + s2v) : -FLT_MAX;
        int rm = lane;                                 // tie -> lowest i -> lowest f
        warp_argmax(rv, rm);
        int jwin = __shfl_sync(FULL, ptr, rm);
        int i1v  = __shfl_sync(FULL, ai, rm);
        int i2v  = __shfl_sync(FULL, bi, jwin);
        if (lane == rm) ptr++;
        if (lane == t) { myval = rv; myidx = i1v * NKEYS + i2v; }
    }

    // Phase C: softmax over the 32 selected (lane 0 holds the max).
    float mx = __shfl_sync(FULL, myval, 0);
    float e = expf(myval - mx);
    float sum = e;
#pragma unroll
    for (int o = 16; o > 0; o >>= 1) sum += __shfl_xor_sync(FULL, sum, o);
    float w = e / sum;
    size_t o = (size_t)(b * HEADS + h) * KNN + lane;
    g_w[o] = w;
    g_idx[o] = myidx;
}

// ---------------------------------------------------------------------------
// K4: out[b,:] = sum over 128 (h,k) of w * values[idx, :]. One block per b.
// 256 threads x float4 = 1024 cols. 2 GiB total gather, coalesced 4KB rows.
// ---------------------------------------------------------------------------
__global__ __launch_bounds__(256) void k4_gather(const float* __restrict__ values,
                                                 float* __restrict__ out) {
    const int b = blockIdx.x;
    __shared__ float sw[HEADS * KNN];
    __shared__ int   sidx[HEADS * KNN];
    const int tid = threadIdx.x;
    if (tid < HEADS * KNN) {
        sw[tid]   = g_w[(size_t)b * HEADS * KNN + tid];
        sidx[tid] = g_idx[(size_t)b * HEADS * KNN + tid];
    }
    __syncthreads();
    float4 acc = make_float4(0.f, 0.f, 0.f, 0.f);
#pragma unroll 4
    for (int e = 0; e < HEADS * KNN; e++) {
        const float4* row = (const float4*)(values + (size_t)sidx[e] * VDIM);
        float4 v = __ldg(row + tid);
        float wt = sw[e];
        acc.x += wt * v.x;
        acc.y += wt * v.y;
        acc.z += wt * v.z;
        acc.w += wt * v.w;
    }
    ((float4*)out)[(size_t)b * (VDIM / 4) + tid] = acc;
}

// ---------------------------------------------------------------------------
extern "C" void kernel_launch(void* const* d_in, const int* in_sizes, int n_in,
                              void* d_out, int out_size) {
    const float* x      = (const float*)d_in[0];  // (4096, 1024)
    const float* wq     = (const float*)d_in[1];  // (1024, 2048)
    const float* keys   = (const float*)d_in[2];  // (4, 2, 512, 256)
    const float* values = (const float*)d_in[3];  // (262144, 1024)
    float* out = (float*)d_out;                   // (4096, 1024)

    k1_gemm<<<dim3(QCOLS / 128, BS / 128), 256>>>(x, wq);
    k2_scores<<<dim3(NKEYS / 128, BS / 128, 8), 256>>>(keys);
    k3_topk<<<BS, 128>>>();
    k4_gather<<<BS, 256>>>(values, out);
}

// round 11
// speedup vs baseline: 1.1033x; 1.1033x over previous
#include <cuda_runtime.h>
#include <cfloat>
#include <math.h>
#include <stdint.h>

#define BS    4096
#define INDIM 1024
#define HEADS 4
#define KDIM  512
#define HALF  256
#define NKEYS 512
#define KNN   32
#define VDIM  1024
#define QCOLS (HEADS*KDIM)   /* 2048 */

// ---------------- scratch (static device arrays; no runtime alloc) ----------
__device__ float g_wT[(size_t)QCOLS * INDIM];              // 8 MB  w^T [N=2048][K=1024]
__device__ float g_q[(size_t)BS * QCOLS];                  // 32 MB
__device__ float g_scores[(size_t)BS * HEADS * 2 * NKEYS]; // 64 MB
__device__ float g_w[(size_t)BS * HEADS * KNN];
__device__ int   g_idx[(size_t)BS * HEADS * KNN];

// ---------------- f32x2 helpers ---------------------------------------------
__device__ __forceinline__ uint64_t pack_dup(float a) {
    uint64_t r;
    asm("mov.b64 %0, {%1, %1};" : "=l"(r) : "f"(a));
    return r;
}
__device__ __forceinline__ uint64_t pack2(float a, float b) {
    uint64_t r;
    asm("mov.b64 %0, {%1, %2};" : "=l"(r) : "f"(a), "f"(b));
    return r;
}
__device__ __forceinline__ void unpack2(uint64_t p, float& a, float& b) {
    asm("mov.b64 {%0, %1}, %2;" : "=f"(a), "=f"(b) : "l"(p));
}
__device__ __forceinline__ void ffma2(uint64_t& acc, uint64_t a, uint64_t b) {
    asm("fma.rn.f32x2 %0, %1, %2, %0;" : "+l"(acc) : "l"(a), "l"(b));
}

// ---------------- conv: w_query [K=1024][N=2048] -> g_wT [N=2048][K=1024] ----
__global__ __launch_bounds__(256) void conv_w_T(const float* __restrict__ w) {
    __shared__ float t[32][33];
    int bx = blockIdx.x * 32;   // n block
    int by = blockIdx.y * 32;   // k block
    int tx = threadIdx.x, ty = threadIdx.y;
#pragma unroll
    for (int j = 0; j < 32; j += 8)
        t[ty + j][tx] = w[(size_t)(by + ty + j) * QCOLS + bx + tx];
    __syncthreads();
#pragma unroll
    for (int j = 0; j < 32; j += 8)
        g_wT[(size_t)(bx + ty + j) * INDIM + by + tx] = t[tx][ty + j];
}

// ---------------- f32x2 SGEMM: C = A * B^T ----------------------------------
// A [M,K], B [N,K], fp32 row-major. CTA tile 128x128, BK=16, 256 threads,
// 8x8 microtile (same mapping as the round-4 passing kernel), packed-pair
// accumulators driven by fma.rn.f32x2. Double-buffered smem, register-staged
// global loads overlapping compute.
#define BK 16

__global__ __launch_bounds__(256, 2)
void gemm_f32x2(const float* __restrict__ A, int lda, int a_z_mult,
                const float* __restrict__ B, int ldb, size_t b_z_stride,
                float* __restrict__ C, int ldc, int c_z_mult, int K) {
    __shared__ float As[2][BK * 128];
    __shared__ float Bs[2][BK * 128];

    const int tid = threadIdx.x;
    const int tr = tid >> 4, tc = tid & 15;
    const int z = blockIdx.z;
    const int bm = blockIdx.y * 128, bn = blockIdx.x * 128;

    const int grow = tid >> 1;            // 0..127
    const int gk   = (tid & 1) * 8;       // 0 or 8

    const float* Ab = A + (size_t)(bm + grow) * lda + (size_t)z * a_z_mult + gk;
    const float* Bb = B + (size_t)z * b_z_stride + (size_t)(bn + grow) * ldb + gk;

    const int NC = K / BK;

    float4 rA0, rA1, rB0, rB1;
    // stage chunk 0
    rA0 = *(const float4*)(Ab);     rA1 = *(const float4*)(Ab + 4);
    rB0 = *(const float4*)(Bb);     rB1 = *(const float4*)(Bb + 4);

    uint64_t acc[8][4];
#pragma unroll
    for (int i = 0; i < 8; i++)
#pragma unroll
        for (int j = 0; j < 4; j++) acc[i][j] = 0ull;

    for (int c = 0; c < NC; c++) {
        const int buf = c & 1;
        // store staged chunk c (transposed: As[k][m], Bs[k][n])
        float* as = &As[buf][0];
        float* bs = &Bs[buf][0];
        as[(gk + 0) * 128 + grow] = rA0.x;
        as[(gk + 1) * 128 + grow] = rA0.y;
        as[(gk + 2) * 128 + grow] = rA0.z;
        as[(gk + 3) * 128 + grow] = rA0.w;
        as[(gk + 4) * 128 + grow] = rA1.x;
        as[(gk + 5) * 128 + grow] = rA1.y;
        as[(gk + 6) * 128 + grow] = rA1.z;
        as[(gk + 7) * 128 + grow] = rA1.w;
        bs[(gk + 0) * 128 + grow] = rB0.x;
        bs[(gk + 1) * 128 + grow] = rB0.y;
        bs[(gk + 2) * 128 + grow] = rB0.z;
        bs[(gk + 3) * 128 + grow] = rB0.w;
        bs[(gk + 4) * 128 + grow] = rB1.x;
        bs[(gk + 5) * 128 + grow] = rB1.y;
        bs[(gk + 6) * 128 + grow] = rB1.z;
        bs[(gk + 7) * 128 + grow] = rB1.w;
        __syncthreads();

        // issue global loads for chunk c+1 (overlap with compute below)
        if (c + 1 < NC) {
            const float* An = Ab + (size_t)(c + 1) * BK;
            const float* Bn = Bb + (size_t)(c + 1) * BK;
            rA0 = *(const float4*)(An);     rA1 = *(const float4*)(An + 4);
            rB0 = *(const float4*)(Bn);     rB1 = *(const float4*)(Bn + 4);
        }

#pragma unroll
        for (int k = 0; k < BK; k++) {
            float4 a0 = *(const float4*)&As[buf][k * 128 + tr * 4];
            float4 a1 = *(const float4*)&As[buf][k * 128 + 64 + tr * 4];
            float4 b0 = *(const float4*)&Bs[buf][k * 128 + tc * 4];
            float4 b1 = *(const float4*)&Bs[buf][k * 128 + 64 + tc * 4];
            uint64_t pb[4] = { pack2(b0.x, b0.y), pack2(b0.z, b0.w),
                               pack2(b1.x, b1.y), pack2(b1.z, b1.w) };
            float af[8] = {a0.x, a0.y, a0.z, a0.w, a1.x, a1.y, a1.z, a1.w};
#pragma unroll
            for (int i = 0; i < 8; i++) {
                uint64_t pa = pack_dup(af[i]);
                ffma2(acc[i][0], pa, pb[0]);
                ffma2(acc[i][1], pa, pb[1]);
                ffma2(acc[i][2], pa, pb[2]);
                ffma2(acc[i][3], pa, pb[3]);
            }
        }
        __syncthreads();
    }

    // epilogue (round-4 mapping: i<4 -> rows tr*4+i, else 64+tr*4+i-4)
#pragma unroll
    for (int i = 0; i < 8; i++) {
        int row = bm + ((i < 4) ? (tr * 4 + i) : (64 + tr * 4 + i - 4));
        float* Crow = C + (size_t)row * ldc + (size_t)z * c_z_mult + bn;
        float c0, c1, c2, c3;
        unpack2(acc[i][0], c0, c1); unpack2(acc[i][1], c2, c3);
        *(float4*)(Crow + tc * 4) = make_float4(c0, c1, c2, c3);
        unpack2(acc[i][2], c0, c1); unpack2(acc[i][3], c2, c3);
        *(float4*)(Crow + 64 + tc * 4) = make_float4(c0, c1, c2, c3);
    }
}

// ---------------- K3: top-k + softmax (unchanged from passing R4) ------------
__device__ __forceinline__ void warp_argmax(float& rv, int& rm) {
#pragma unroll
    for (int o = 16; o > 0; o >>= 1) {
        float ov = __shfl_down_sync(0xffffffffu, rv, o);
        int   om = __shfl_down_sync(0xffffffffu, rm, o);
        if (ov > rv || (ov == rv && om < rm)) { rv = ov; rm = om; }
    }
    rv = __shfl_sync(0xffffffffu, rv, 0);
    rm = __shfl_sync(0xffffffffu, rm, 0);
}

__global__ __launch_bounds__(128) void k3_topk() {
    const unsigned FULL = 0xffffffffu;
    const int b = blockIdx.x;
    const int h = threadIdx.x >> 5;
    const int lane = threadIdx.x & 31;

    float selv[2];
    int   seli[2];
#pragma unroll
    for (int s = 0; s < 2; s++) {
        const float* S = g_scores + ((size_t)(b * HEADS + h) * 2 + s) * NKEYS;
        float v[16];
#pragma unroll
        for (int i = 0; i < 16; i++) v[i] = S[i * 32 + lane];
        float mysel = 0.f; int myi = 0;
        for (int t = 0; t < KNN; t++) {
            float lv = -FLT_MAX; int ls = 0;
#pragma unroll
            for (int i = 0; i < 16; i++)
                if (v[i] > lv) { lv = v[i]; ls = i; }
            float rv = lv; int rm = ls * 32 + lane;
            warp_argmax(rv, rm);
            if ((rm & 31) == lane) v[rm >> 5] = -FLT_MAX;
            if (lane == t) { mysel = rv; myi = rm; }
        }
        selv[s] = mysel; seli[s] = myi;
    }

    const float av = selv[0]; const int ai = seli[0];
    const float bv = selv[1]; const int bi = seli[1];
    int ptr = 0;
    float myval = 0.f; int myidx = 0;
    for (int t = 0; t < KNN; t++) {
        float s2v = __shfl_sync(FULL, bv, ptr & 31);
        float rv = (ptr < KNN) ? (av + s2v) : -FLT_MAX;
        int rm = lane;
        warp_argmax(rv, rm);
        int jwin = __shfl_sync(FULL, ptr, rm);
        int i1v  = __shfl_sync(FULL, ai, rm);
        int i2v  = __shfl_sync(FULL, bi, jwin);
        if (lane == rm) ptr++;
        if (lane == t) { myval = rv; myidx = i1v * NKEYS + i2v; }
    }

    float mx = __shfl_sync(FULL, myval, 0);
    float e = expf(myval - mx);
    float sum = e;
#pragma unroll
    for (int o = 16; o > 0; o >>= 1) sum += __shfl_xor_sync(FULL, sum, o);
    float w = e / sum;
    size_t o = (size_t)(b * HEADS + h) * KNN + lane;
    g_w[o] = w;
    g_idx[o] = myidx;
}

// ---------------- K4: gather + weighted bag (at HBM roofline) ---------------
__global__ __launch_bounds__(256) void k4_gather(const float* __restrict__ values,
                                                 float* __restrict__ out) {
    const int b = blockIdx.x;
    __shared__ float sw[HEADS * KNN];
    __shared__ int   sidx[HEADS * KNN];
    const int tid = threadIdx.x;
    if (tid < HEADS * KNN) {
        sw[tid]   = g_w[(size_t)b * HEADS * KNN + tid];
        sidx[tid] = g_idx[(size_t)b * HEADS * KNN + tid];
    }
    __syncthreads();
    float4 acc = make_float4(0.f, 0.f, 0.f, 0.f);
#pragma unroll 4
    for (int e = 0; e < HEADS * KNN; e++) {
        const float4* row = (const float4*)(values + (size_t)sidx[e] * VDIM);
        float4 v = __ldg(row + tid);
        float wt = sw[e];
        acc.x += wt * v.x;
        acc.y += wt * v.y;
        acc.z += wt * v.z;
        acc.w += wt * v.w;
    }
    ((float4*)out)[(size_t)b * (VDIM / 4) + tid] = acc;
}

// ---------------------------------------------------------------------------
extern "C" void kernel_launch(void* const* d_in, const int* in_sizes, int n_in,
                              void* d_out, int out_size) {
    const float* x      = (const float*)d_in[0];  // (4096, 1024)
    const float* wq     = (const float*)d_in[1];  // (1024, 2048)
    const float* keys   = (const float*)d_in[2];  // (4, 2, 512, 256)
    const float* values = (const float*)d_in[3];  // (262144, 1024)
    float* out = (float*)d_out;                   // (4096, 1024)

    float *wT, *q, *scores;
    cudaGetSymbolAddress((void**)&wT, g_wT);
    cudaGetSymbolAddress((void**)&q, g_q);
    cudaGetSymbolAddress((void**)&scores, g_scores);

    // transpose w_query (only prep: both GEMMs uniform NT, fp32 end-to-end)
    conv_w_T<<<dim3(QCOLS / 32, INDIM / 32), dim3(32, 8)>>>(wq);

    // K1: q = x @ w_query
    gemm_f32x2<<<dim3(QCOLS / 128, BS / 128, 1), 256>>>(
        x, INDIM, 0,
        wT, INDIM, 0,
        q, QCOLS, 0, INDIM);

    // K2: scores[b, z*512+n] = q[b, z*256:+256] . keys[z][n, :]
    gemm_f32x2<<<dim3(NKEYS / 128, BS / 128, HEADS * 2), 256>>>(
        q, QCOLS, HALF,
        keys, HALF, (size_t)NKEYS * HALF,
        scores, HEADS * 2 * NKEYS, NKEYS, HALF);

    k3_topk<<<BS, 128>>>();
    k4_gather<<<BS, 256>>>(values, out);
}

// round 15
// speedup vs baseline: 1.3158x; 1.1926x over previous
#include <cuda_runtime.h>
#include <cfloat>
#include <math.h>
#include <stdint.h>

#define BS    4096
#define INDIM 1024
#define HEADS 4
#define KDIM  512
#define HALF  256
#define NKEYS 512
#define KNN   32
#define VDIM  1024
#define QCOLS (HEADS*KDIM)   /* 2048 */

// ---------------- scratch (static device arrays; no runtime alloc) ----------
__device__ float g_wT[(size_t)QCOLS * INDIM];              // 8 MB  w^T [N=2048][K=1024]
__device__ float g_q[(size_t)BS * QCOLS];                  // 32 MB
__device__ float g_scores[(size_t)BS * HEADS * 2 * NKEYS]; // 64 MB

// ---------------- f32x2 helpers ---------------------------------------------
__device__ __forceinline__ uint64_t pack_dup(float a) {
    uint64_t r;
    asm("mov.b64 %0, {%1, %1};" : "=l"(r) : "f"(a));
    return r;
}
__device__ __forceinline__ void unpack2(uint64_t p, float& a, float& b) {
    asm("mov.b64 {%0, %1}, %2;" : "=f"(a), "=f"(b) : "l"(p));
}
__device__ __forceinline__ void ffma2(uint64_t& acc, uint64_t a, uint64_t b) {
    asm("fma.rn.f32x2 %0, %1, %2, %0;" : "+l"(acc) : "l"(a), "l"(b));
}

// ---------------- conv: w_query [K=1024][N=2048] -> g_wT [N=2048][K=1024] ----
__global__ __launch_bounds__(256) void conv_w_T(const float* __restrict__ w) {
    __shared__ float t[32][33];
    int bx = blockIdx.x * 32;   // n block
    int by = blockIdx.y * 32;   // k block
    int tx = threadIdx.x, ty = threadIdx.y;
#pragma unroll
    for (int j = 0; j < 32; j += 8)
        t[ty + j][tx] = w[(size_t)(by + ty + j) * QCOLS + bx + tx];
    __syncthreads();
#pragma unroll
    for (int j = 0; j < 32; j += 8)
        g_wT[(size_t)(bx + ty + j) * INDIM + by + tx] = t[tx][ty + j];
}

// ---------------- f32x2 SGEMM: C = A * B^T ----------------------------------
// A [M,K], B [N,K], fp32 row-major. CTA tile 128x128, BK=16, 256 threads,
// 8x8 microtile, packed-pair accumulators via fma.rn.f32x2. Double-buffered
// smem, register-staged global loads. B pairs loaded as ulonglong2 (no packing).
#define BK 16

__global__ __launch_bounds__(256, 2)
void gemm_f32x2(const float* __restrict__ A, int lda, int a_z_mult,
                const float* __restrict__ B, int ldb, size_t b_z_stride,
                float* __restrict__ C, int ldc, int c_z_mult, int K) {
    __shared__ __align__(16) float As[2][BK * 128];
    __shared__ __align__(16) float Bs[2][BK * 128];

    const int tid = threadIdx.x;
    const int tr = tid >> 4, tc = tid & 15;
    const int z = blockIdx.z;
    const int bm = blockIdx.y * 128, bn = blockIdx.x * 128;

    const int grow = tid >> 1;            // 0..127
    const int gk   = (tid & 1) * 8;       // 0 or 8

    const float* Ab = A + (size_t)(bm + grow) * lda + (size_t)z * a_z_mult + gk;
    const float* Bb = B + (size_t)z * b_z_stride + (size_t)(bn + grow) * ldb + gk;

    const int NC = K / BK;

    float4 rA0, rA1, rB0, rB1;
    rA0 = *(const float4*)(Ab);     rA1 = *(const float4*)(Ab + 4);
    rB0 = *(const float4*)(Bb);     rB1 = *(const float4*)(Bb + 4);

    uint64_t acc[8][4];
#pragma unroll
    for (int i = 0; i < 8; i++)
#pragma unroll
        for (int j = 0; j < 4; j++) acc[i][j] = 0ull;

    for (int c = 0; c < NC; c++) {
        const int buf = c & 1;
        float* as = &As[buf][0];
        float* bs = &Bs[buf][0];
        as[(gk + 0) * 128 + grow] = rA0.x;
        as[(gk + 1) * 128 + grow] = rA0.y;
        as[(gk + 2) * 128 + grow] = rA0.z;
        as[(gk + 3) * 128 + grow] = rA0.w;
        as[(gk + 4) * 128 + grow] = rA1.x;
        as[(gk + 5) * 128 + grow] = rA1.y;
        as[(gk + 6) * 128 + grow] = rA1.z;
        as[(gk + 7) * 128 + grow] = rA1.w;
        bs[(gk + 0) * 128 + grow] = rB0.x;
        bs[(gk + 1) * 128 + grow] = rB0.y;
        bs[(gk + 2) * 128 + grow] = rB0.z;
        bs[(gk + 3) * 128 + grow] = rB0.w;
        bs[(gk + 4) * 128 + grow] = rB1.x;
        bs[(gk + 5) * 128 + grow] = rB1.y;
        bs[(gk + 6) * 128 + grow] = rB1.z;
        bs[(gk + 7) * 128 + grow] = rB1.w;
        __syncthreads();

        if (c + 1 < NC) {
            const float* An = Ab + (size_t)(c + 1) * BK;
            const float* Bn = Bb + (size_t)(c + 1) * BK;
            rA0 = *(const float4*)(An);     rA1 = *(const float4*)(An + 4);
            rB0 = *(const float4*)(Bn);     rB1 = *(const float4*)(Bn + 4);
        }

#pragma unroll
        for (int k = 0; k < BK; k++) {
            float4 a0 = *(const float4*)&As[buf][k * 128 + tr * 4];
            float4 a1 = *(const float4*)&As[buf][k * 128 + 64 + tr * 4];
            ulonglong2 pb01 = *(const ulonglong2*)&Bs[buf][k * 128 + tc * 4];
            ulonglong2 pb23 = *(const ulonglong2*)&Bs[buf][k * 128 + 64 + tc * 4];
            uint64_t pb[4] = { pb01.x, pb01.y, pb23.x, pb23.y };
            float af[8] = {a0.x, a0.y, a0.z, a0.w, a1.x, a1.y, a1.z, a1.w};
#pragma unroll
            for (int i = 0; i < 8; i++) {
                uint64_t pa = pack_dup(af[i]);
                ffma2(acc[i][0], pa, pb[0]);
                ffma2(acc[i][1], pa, pb[1]);
                ffma2(acc[i][2], pa, pb[2]);
                ffma2(acc[i][3], pa, pb[3]);
            }
        }
        __syncthreads();
    }

#pragma unroll
    for (int i = 0; i < 8; i++) {
        int row = bm + ((i < 4) ? (tr * 4 + i) : (64 + tr * 4 + i - 4));
        float* Crow = C + (size_t)row * ldc + (size_t)z * c_z_mult + bn;
        float c0, c1, c2, c3;
        unpack2(acc[i][0], c0, c1); unpack2(acc[i][1], c2, c3);
        *(float4*)(Crow + tc * 4) = make_float4(c0, c1, c2, c3);
        unpack2(acc[i][2], c0, c1); unpack2(acc[i][3], c2, c3);
        *(float4*)(Crow + 64 + tc * 4) = make_float4(c0, c1, c2, c3);
    }
}

// ---------------- fused top-k + softmax + gather -----------------------------
// One block per b. Warps 0..7: phase A top-32-of-512 for (h = w>>1, s = w&1).
// Warps 0..3: phase B staircase + softmax for h = w. Then all 256 threads
// gather 128 rows of values (DRAM-bound) — overlaps other blocks' ALU phases.
__device__ __forceinline__ void warp_argmax(float& rv, int& rm) {
#pragma unroll
    for (int o = 16; o > 0; o >>= 1) {
        float ov = __shfl_down_sync(0xffffffffu, rv, o);
        int   om = __shfl_down_sync(0xffffffffu, rm, o);
        if (ov > rv || (ov == rv && om < rm)) { rv = ov; rm = om; }
    }
    rv = __shfl_sync(0xffffffffu, rv, 0);
    rm = __shfl_sync(0xffffffffu, rm, 0);
}

__global__ __launch_bounds__(256) void k34_fused(const float* __restrict__ values,
                                                 float* __restrict__ out) {
    const unsigned FULL = 0xffffffffu;
    const int b = blockIdx.x;
    const int tid = threadIdx.x;
    const int w = tid >> 5, lane = tid & 31;

    __shared__ float sv[HEADS][2][KNN];
    __shared__ int   si[HEADS][2][KNN];
    __shared__ float sw[HEADS * KNN];
    __shared__ int   sidx[HEADS * KNN];

    // Phase A: 8 warps, one per (h, s)
    {
        const int h = w >> 1, s = w & 1;
        const float* S = g_scores + ((size_t)(b * HEADS + h) * 2 + s) * NKEYS;
        float v[16];
#pragma unroll
        for (int i = 0; i < 16; i++) v[i] = S[i * 32 + lane];
        float mysel = 0.f; int myi = 0;
        for (int t = 0; t < KNN; t++) {
            float lv = -FLT_MAX; int ls = 0;
#pragma unroll
            for (int i = 0; i < 16; i++)
                if (v[i] > lv) { lv = v[i]; ls = i; }
            float rv = lv; int rm = ls * 32 + lane;   // element index (tie -> lowest)
            warp_argmax(rv, rm);
            if ((rm & 31) == lane) v[rm >> 5] = -FLT_MAX;
            if (lane == t) { mysel = rv; myi = rm; }
        }
        sv[h][s][lane] = mysel;
        si[h][s][lane] = myi;
    }
    __syncthreads();

    // Phase B: 4 warps, one per h — staircase top-32 of sorted-sum grid + softmax
    if (w < HEADS) {
        const int h = w;
        const float av = sv[h][0][lane]; const int ai = si[h][0][lane];
        const float bv = sv[h][1][lane]; const int bi = si[h][1][lane];
        int ptr = 0;
        float myval = 0.f; int myidx = 0;
        for (int t = 0; t < KNN; t++) {
            float s2v = __shfl_sync(FULL, bv, ptr & 31);
            float rv = (ptr < KNN) ? (av + s2v) : -FLT_MAX;
            int rm = lane;                            // tie -> lowest i -> lowest f
            warp_argmax(rv, rm);
            int jwin = __shfl_sync(FULL, ptr, rm);
            int i1v  = __shfl_sync(FULL, ai, rm);
            int i2v  = __shfl_sync(FULL, bi, jwin);
            if (lane == rm) ptr++;
            if (lane == t) { myval = rv; myidx = i1v * NKEYS + i2v; }
        }
        float mx = __shfl_sync(FULL, myval, 0);
        float e = expf(myval - mx);
        float sum = e;
#pragma unroll
        for (int o = 16; o > 0; o >>= 1) sum += __shfl_xor_sync(FULL, sum, o);
        sw[h * KNN + lane]   = e / sum;
        sidx[h * KNN + lane] = myidx;
    }
    __syncthreads();

    // Phase C: gather + weighted bag, all 256 threads (same order as round-4 k4)
    float4 acc = make_float4(0.f, 0.f, 0.f, 0.f);
#pragma unroll 4
    for (int e = 0; e < HEADS * KNN; e++) {
        const float4* row = (const float4*)(values + (size_t)sidx[e] * VDIM);
        float4 v = __ldg(row + tid);
        float wt = sw[e];
        acc.x += wt * v.x;
        acc.y += wt * v.y;
        acc.z += wt * v.z;
        acc.w += wt * v.w;
    }
    ((float4*)out)[(size_t)b * (VDIM / 4) + tid] = acc;
}

// ---------------------------------------------------------------------------
extern "C" void kernel_launch(void* const* d_in, const int* in_sizes, int n_in,
                              void* d_out, int out_size) {
    const float* x      = (const float*)d_in[0];  // (4096, 1024)
    const float* wq     = (const float*)d_in[1];  // (1024, 2048)
    const float* keys   = (const float*)d_in[2];  // (4, 2, 512, 256)
    const float* values = (const float*)d_in[3];  // (262144, 1024)
    float* out = (float*)d_out;                   // (4096, 1024)

    float *wT, *q, *scores;
    cudaGetSymbolAddress((void**)&wT, g_wT);
    cudaGetSymbolAddress((void**)&q, g_q);
    cudaGetSymbolAddress((void**)&scores, g_scores);

    // transpose w_query (both GEMMs uniform NT, fp32 end-to-end)
    conv_w_T<<<dim3(QCOLS / 32, INDIM / 32), dim3(32, 8)>>>(wq);

    // K1: q = x @ w_query
    gemm_f32x2<<<dim3(QCOLS / 128, BS / 128, 1), 256>>>(
        x, INDIM, 0,
        wT, INDIM, 0,
        q, QCOLS, 0, INDIM);

    // K2: scores[b, z*512+n] = q[b, z*256:+256] . keys[z][n, :]
    gemm_f32x2<<<dim3(NKEYS / 128, BS / 128, HEADS * 2), 256>>>(
        q, QCOLS, HALF,
        keys, HALF, (size_t)NKEYS * HALF,
        scores, HEADS * 2 * NKEYS, NKEYS, HALF);

    // fused top-k + softmax + gather (ALU phase overlaps DRAM phase across blocks)
    k34_fused<<<BS, 256>>>(values, out);
}